// round 1
// baseline (speedup 1.0000x reference)
#include <cuda_runtime.h>

// IGANN: logits[b] = x[b,:]@a + bias + sum_f fc3_f(relu(fc2_f(relu(x[b,f]*W1_f + b1_f))))
// B=32768, F=256, H=16. fp32 throughout.
//
// Strategy: FMA-bound kernel. Grid = (batch tiles) x (feature chunks).
// Weights + coalesced-staged x tile in smem; 2 rows per thread so each
// broadcast weight load feeds 2 FMAs; fc3 fused into the k-loop.

constexpr int B_TOTAL = 32768;
constexpr int F_TOTAL = 256;
constexpr int H       = 16;

constexpr int BLOCK   = 256;   // threads
constexpr int RPT     = 2;     // rows per thread
constexpr int ROWS    = BLOCK * RPT;      // 512 rows per block
constexpr int FCHUNK  = 32;    // features per block
constexpr int NCHUNK  = F_TOTAL / FCHUNK; // 8
constexpr int NBTILE  = B_TOTAL / ROWS;   // 64
constexpr int XSTRIDE = FCHUNK + 1;       // 33: conflict-free column reads

// smem layout (floats)
constexpr int SX_ELE  = ROWS * XSTRIDE;        // 16896
constexpr int W1_ELE  = FCHUNK * H;            // 512
constexpr int W2_ELE  = FCHUNK * H * H;        // 8192
constexpr int SMEM_FLOATS = SX_ELE + 4 * W1_ELE + W2_ELE + 2 * FCHUNK;
constexpr int SMEM_BYTES  = SMEM_FLOATS * (int)sizeof(float);   // 108,800 B

__global__ void igann_init_kernel(float* __restrict__ out,
                                  const float* __restrict__ bias_b) {
    int i = blockIdx.x * blockDim.x + threadIdx.x;
    if (i < B_TOTAL) out[i] = bias_b[0];
}

__global__ __launch_bounds__(BLOCK)
void igann_kernel(const float* __restrict__ x,
                  const float* __restrict__ linear_a,
                  const float* __restrict__ W1,
                  const float* __restrict__ b1,
                  const float* __restrict__ W2,
                  const float* __restrict__ b2,
                  const float* __restrict__ W3,
                  const float* __restrict__ b3,
                  float* __restrict__ out) {
    extern __shared__ float smem[];
    float* sx  = smem;                    // [ROWS][XSTRIDE]
    float* sW1 = sx  + SX_ELE;            // [FCHUNK][H]
    float* sB1 = sW1 + W1_ELE;
    float* sB2 = sB1 + W1_ELE;
    float* sW3 = sB2 + W1_ELE;
    float* sW2 = sW3 + W1_ELE;            // [FCHUNK][H][H]  (k-major, h contiguous)
    float* sB3 = sW2 + W2_ELE;            // [FCHUNK]
    float* sA  = sB3 + FCHUNK;            // [FCHUNK]

    const int tid  = threadIdx.x;
    const int row0 = blockIdx.x * ROWS;   // batch tile base
    const int f0   = blockIdx.y * FCHUNK; // feature chunk base

    // ---- stage weights ----
    {
        const int wbase = f0 * H;
        for (int i = tid; i < FCHUNK * H; i += BLOCK) {
            sW1[i] = W1[wbase + i];
            sB1[i] = b1[wbase + i];
            sB2[i] = b2[wbase + i];
            sW3[i] = W3[wbase + i];
        }
        const int w2base = f0 * H * H;
        for (int i = tid; i < W2_ELE; i += BLOCK) sW2[i] = W2[w2base + i];
        if (tid < FCHUNK) {
            sB3[tid] = b3[f0 + tid];
            sA[tid]  = linear_a[f0 + tid];
        }
    }

    // ---- stage x tile, coalesced along features ----
    // i % FCHUNK is the feature column; with FCHUNK=32 a warp reads one row's
    // 32 contiguous floats (128B).
    for (int i = tid; i < ROWS * FCHUNK; i += BLOCK) {
        const int r = i / FCHUNK;
        const int c = i - r * FCHUNK;
        sx[r * XSTRIDE + c] = x[(row0 + r) * F_TOTAL + f0 + c];
    }
    __syncthreads();

    float acc0 = 0.0f, acc1 = 0.0f;
    const int r0 = tid;            // row A within tile
    const int r1 = tid + BLOCK;    // row B within tile

    for (int f = 0; f < FCHUNK; ++f) {
        const float x0 = sx[r0 * XSTRIDE + f];
        const float x1 = sx[r1 * XSTRIDE + f];

        const float* w1 = sW1 + f * H;
        const float* bb1 = sB1 + f * H;
        float h1a[H], h1b[H];
        #pragma unroll
        for (int h = 0; h < H; ++h) {
            h1a[h] = fmaxf(fmaf(x0, w1[h], bb1[h]), 0.0f);
            h1b[h] = fmaxf(fmaf(x1, w1[h], bb1[h]), 0.0f);
        }

        const float* w2f = sW2 + f * H * H;
        const float* bb2 = sB2 + f * H;
        const float* w3  = sW3 + f * H;
        #pragma unroll
        for (int k = 0; k < H; ++k) {
            float t0 = bb2[k];
            float t1 = t0;
            const float* w2r = w2f + k * H;
            #pragma unroll
            for (int h = 0; h < H; ++h) {
                const float w = w2r[h];
                t0 = fmaf(h1a[h], w, t0);
                t1 = fmaf(h1b[h], w, t1);
            }
            t0 = fmaxf(t0, 0.0f);
            t1 = fmaxf(t1, 0.0f);
            const float w3k = w3[k];
            acc0 = fmaf(t0, w3k, acc0);
            acc1 = fmaf(t1, w3k, acc1);
        }

        const float bf = sB3[f];
        const float af = sA[f];
        acc0 = fmaf(x0, af, acc0 + bf);
        acc1 = fmaf(x1, af, acc1 + bf);
    }

    atomicAdd(&out[row0 + r0], acc0);
    atomicAdd(&out[row0 + r1], acc1);
}

extern "C" void kernel_launch(void* const* d_in, const int* in_sizes, int n_in,
                              void* d_out, int out_size) {
    const float* x        = (const float*)d_in[0];
    const float* linear_a = (const float*)d_in[1];
    const float* bias_b   = (const float*)d_in[2];
    const float* W1       = (const float*)d_in[3];
    const float* b1       = (const float*)d_in[4];
    const float* W2       = (const float*)d_in[5];
    const float* b2       = (const float*)d_in[6];
    const float* W3       = (const float*)d_in[7];
    const float* b3       = (const float*)d_in[8];
    float* out = (float*)d_out;

    cudaFuncSetAttribute(igann_kernel,
                         cudaFuncAttributeMaxDynamicSharedMemorySize, SMEM_BYTES);

    igann_init_kernel<<<(B_TOTAL + 255) / 256, 256>>>(out, bias_b);

    dim3 grid(NBTILE, NCHUNK);
    igann_kernel<<<grid, BLOCK, SMEM_BYTES>>>(x, linear_a, W1, b1, W2, b2, W3, b3, out);
}

// round 4
// speedup vs baseline: 1.3107x; 1.3107x over previous
#include <cuda_runtime.h>

// IGANN GAM: logits[b] = x[b,:]@a + bias + sum_f fc3_f(relu(fc2_f(relu(x[b,f]*W1_f+b1_f))))
// B=32768, F=256, H=16, fp32.
//
// R2: fma.rn.f32x2 (FFMA2) packed across output-k pairs; W2 restaged as
// k-pair-interleaved 64-bit elements so LDS.128 feeds FFMA2 directly.
// FCHUNK=16 + launch_bounds(256,3) -> 24 warps/SM.

typedef unsigned long long ull;

constexpr int B_TOTAL = 32768;
constexpr int F_TOTAL = 256;
constexpr int H       = 16;

constexpr int BLOCK   = 256;
constexpr int RPT     = 2;
constexpr int ROWS    = BLOCK * RPT;        // 512
constexpr int FCHUNK  = 16;
constexpr int NCHUNK  = F_TOTAL / FCHUNK;   // 16
constexpr int NBTILE  = B_TOTAL / ROWS;     // 64
constexpr int XSTRIDE = FCHUNK + 1;         // 17

// smem layout (floats), pair arrays first for 16B alignment
constexpr int W2P_ELE = FCHUNK * H * (H / 2) * 2;  // 4096 (16KB), [f][h][kp]{lo,hi}
constexpr int W1D_ELE = FCHUNK * H * 2;            // 512 dup pairs
constexpr int SX_ELE  = ROWS * XSTRIDE;            // 8704
constexpr int SMEM_FLOATS = W2P_ELE + 2 * W1D_ELE + 2 * FCHUNK * H + 2 * FCHUNK + SX_ELE;
constexpr int SMEM_BYTES  = SMEM_FLOATS * (int)sizeof(float);  // ~57.5KB

__device__ __forceinline__ ull fma2(ull a, ull b, ull c) {
    ull d;
    asm("fma.rn.f32x2 %0, %1, %2, %3;" : "=l"(d) : "l"(a), "l"(b), "l"(c));
    return d;
}
__device__ __forceinline__ ull pack2(float lo, float hi) {
    ull d;
    asm("mov.b64 %0, {%1, %2};" : "=l"(d) : "f"(lo), "f"(hi));
    return d;
}
__device__ __forceinline__ void unpack2(ull v, float& lo, float& hi) {
    asm("mov.b64 {%0, %1}, %2;" : "=f"(lo), "=f"(hi) : "l"(v));
}

__global__ void igann_init_kernel(float* __restrict__ out,
                                  const float* __restrict__ bias_b) {
    int i = blockIdx.x * blockDim.x + threadIdx.x;
    if (i < B_TOTAL) out[i] = bias_b[0];
}

__global__ __launch_bounds__(BLOCK, 3)
void igann_kernel(const float* __restrict__ x,
                  const float* __restrict__ linear_a,
                  const float* __restrict__ W1,
                  const float* __restrict__ b1,
                  const float* __restrict__ W2,
                  const float* __restrict__ b2,
                  const float* __restrict__ W3,
                  const float* __restrict__ b3,
                  float* __restrict__ out) {
    extern __shared__ float smem[];
    float* sW2p = smem;                      // [FCHUNK][H][H/2][2]  k-pair interleaved
    float* sW1d = sW2p + W2P_ELE;            // [FCHUNK][H][2] duplicated
    float* sB1d = sW1d + W1D_ELE;            // [FCHUNK][H][2] duplicated
    float* sB2  = sB1d + W1D_ELE;            // [FCHUNK][H] (read as ull pairs)
    float* sW3  = sB2  + FCHUNK * H;         // [FCHUNK][H]
    float* sB3  = sW3  + FCHUNK * H;         // [FCHUNK]
    float* sA   = sB3  + FCHUNK;             // [FCHUNK]
    float* sx   = sA   + FCHUNK;             // [ROWS][XSTRIDE]

    const int tid  = threadIdx.x;
    const int row0 = blockIdx.x * ROWS;
    const int f0   = blockIdx.y * FCHUNK;

    // ---- stage small weights ----
    {
        const int wbase = f0 * H;
        for (int i = tid; i < FCHUNK * H; i += BLOCK) {
            const float w = W1[wbase + i];
            sW1d[2 * i] = w; sW1d[2 * i + 1] = w;
            const float bb = b1[wbase + i];
            sB1d[2 * i] = bb; sB1d[2 * i + 1] = bb;
            sB2[i] = b2[wbase + i];
            sW3[i] = W3[wbase + i];
        }
        if (tid < FCHUNK) {
            sB3[tid] = b3[f0 + tid];
            sA[tid]  = linear_a[f0 + tid];
        }
    }
    // ---- stage W2 as k-pair interleaved: sW2p[f][h][kp] = {W2[f][2kp][h], W2[f][2kp+1][h]}
    for (int i = tid; i < FCHUNK * H * (H / 2); i += BLOCK) {
        const int f  = i >> 7;          // /128
        const int h  = (i >> 3) & 15;
        const int kp = i & 7;
        const float* src = W2 + (f0 + f) * (H * H) + h;
        sW2p[2 * i]     = src[(2 * kp) * H];
        sW2p[2 * i + 1] = src[(2 * kp + 1) * H];
    }
    // ---- stage x tile (coalesced 64B rows) ----
    for (int i = tid; i < ROWS * FCHUNK; i += BLOCK) {
        const int r = i >> 4;
        const int c = i & 15;
        sx[r * XSTRIDE + c] = x[(row0 + r) * F_TOTAL + f0 + c];
    }
    __syncthreads();

    float acc0a = 0.0f, acc0b = 0.0f, acc1a = 0.0f, acc1b = 0.0f;
    const int r0 = tid;
    const int r1 = tid + BLOCK;

    for (int f = 0; f < FCHUNK; ++f) {
        const float x0 = sx[r0 * XSTRIDE + f];
        const float x1 = sx[r1 * XSTRIDE + f];
        const ull xp = pack2(x0, x1);

        const ull* w1d = (const ull*)sW1d + f * H;
        const ull* b1d = (const ull*)sB1d + f * H;
        const ull* b2p = (const ull*)(sB2 + f * H);               // 8 k-pairs
        const ulonglong2* w2q = (const ulonglong2*)sW2p + f * 64; // 16h x 4 quads

        ull ta[8], tb[8];   // {t_2k, t_2k+1} per row
        #pragma unroll
        for (int h = 0; h < H; ++h) {
            // h1 for both rows in one FFMA2, then relu scalar
            const ull hp = fma2(xp, w1d[h], b1d[h]);
            float ha, hb; unpack2(hp, ha, hb);
            ha = fmaxf(ha, 0.0f);
            hb = fmaxf(hb, 0.0f);
            const ull da = pack2(ha, ha);
            const ull db = pack2(hb, hb);
            const ulonglong2* wr = w2q + h * 4;
            #pragma unroll
            for (int j = 0; j < 4; ++j) {
                const ulonglong2 w = wr[j];   // LDS.128: k-pairs 2j and 2j+1
                if (h == 0) {
                    const ull c0 = b2p[2 * j];
                    const ull c1 = b2p[2 * j + 1];
                    ta[2 * j]     = fma2(da, w.x, c0);
                    tb[2 * j]     = fma2(db, w.x, c0);
                    ta[2 * j + 1] = fma2(da, w.y, c1);
                    tb[2 * j + 1] = fma2(db, w.y, c1);
                } else {
                    ta[2 * j]     = fma2(da, w.x, ta[2 * j]);
                    tb[2 * j]     = fma2(db, w.x, tb[2 * j]);
                    ta[2 * j + 1] = fma2(da, w.y, ta[2 * j + 1]);
                    tb[2 * j + 1] = fma2(db, w.y, tb[2 * j + 1]);
                }
            }
        }
        // epilogue: relu(t) dot W3, two acc chains per row
        #pragma unroll
        for (int kp = 0; kp < 8; ++kp) {
            float alo, ahi, blo, bhi;
            unpack2(ta[kp], alo, ahi);
            unpack2(tb[kp], blo, bhi);
            const float w3a = sW3[f * H + 2 * kp];
            const float w3b = sW3[f * H + 2 * kp + 1];
            acc0a = fmaf(fmaxf(alo, 0.0f), w3a, acc0a);
            acc0b = fmaf(fmaxf(ahi, 0.0f), w3b, acc0b);
            acc1a = fmaf(fmaxf(blo, 0.0f), w3a, acc1a);
            acc1b = fmaf(fmaxf(bhi, 0.0f), w3b, acc1b);
        }
        const float bf = sB3[f];
        const float af = sA[f];
        acc0a = fmaf(x0, af, acc0a + bf);
        acc1a = fmaf(x1, af, acc1a + bf);
    }

    atomicAdd(&out[row0 + r0], acc0a + acc0b);
    atomicAdd(&out[row0 + r1], acc1a + acc1b);
}

extern "C" void kernel_launch(void* const* d_in, const int* in_sizes, int n_in,
                              void* d_out, int out_size) {
    const float* x        = (const float*)d_in[0];
    const float* linear_a = (const float*)d_in[1];
    const float* bias_b   = (const float*)d_in[2];
    const float* W1       = (const float*)d_in[3];
    const float* b1       = (const float*)d_in[4];
    const float* W2       = (const float*)d_in[5];
    const float* b2       = (const float*)d_in[6];
    const float* W3       = (const float*)d_in[7];
    const float* b3       = (const float*)d_in[8];
    float* out = (float*)d_out;

    cudaFuncSetAttribute(igann_kernel,
                         cudaFuncAttributeMaxDynamicSharedMemorySize, SMEM_BYTES);

    igann_init_kernel<<<(B_TOTAL + 255) / 256, 256>>>(out, bias_b);

    dim3 grid(NBTILE, NCHUNK);
    igann_kernel<<<grid, BLOCK, SMEM_BYTES>>>(x, linear_a, W1, b1, W2, b2, W3, b3, out);
}

// round 7
// speedup vs baseline: 1.3389x; 1.0215x over previous
#include <cuda_runtime.h>

// IGANN GAM: logits[b] = x[b,:]@a + bias + sum_f fc3_f(relu(fc2_f(relu(x[b,f]*W1_f+b1_f))))
// B=32768, F=256, H=16, fp32.
//
// R4: RPT=4 rows/thread (each W2 LDS.128 feeds 8 FFMA2), FFMA2 epilogue with
// pre-paired W3, FCHUNK=8, 2 CTAs/SM (reg cap 128).

typedef unsigned long long ull;

constexpr int B_TOTAL = 32768;
constexpr int F_TOTAL = 256;
constexpr int H       = 16;

constexpr int BLOCK   = 256;
constexpr int RPT     = 4;
constexpr int ROWS    = BLOCK * RPT;        // 1024
constexpr int FCHUNK  = 8;
constexpr int NCHUNK  = F_TOTAL / FCHUNK;   // 32
constexpr int NBTILE  = B_TOTAL / ROWS;     // 32
constexpr int XSTRIDE = FCHUNK + 1;         // 9 (gcd(9,32)=1: conflict-free col reads)

// smem layout (floats); pair arrays first for 16B alignment
constexpr int W2P_ELE = FCHUNK * H * (H / 2) * 2;  // 2048: [f][h][kp]{lo,hi}
constexpr int W1D_ELE = FCHUNK * H * 2;            // 256 dup pairs
constexpr int W3P_ELE = FCHUNK * (H / 2) * 2;      // 128: [f][kp]{lo,hi}
constexpr int SX_ELE  = ROWS * XSTRIDE;            // 9216
constexpr int SMEM_FLOATS = W2P_ELE + 2 * W1D_ELE + FCHUNK * H + W3P_ELE
                          + 2 * FCHUNK + SX_ELE;
constexpr int SMEM_BYTES  = SMEM_FLOATS * (int)sizeof(float);  // ~48.2KB

__device__ __forceinline__ ull fma2(ull a, ull b, ull c) {
    ull d;
    asm("fma.rn.f32x2 %0, %1, %2, %3;" : "=l"(d) : "l"(a), "l"(b), "l"(c));
    return d;
}
__device__ __forceinline__ ull pack2(float lo, float hi) {
    ull d;
    asm("mov.b64 %0, {%1, %2};" : "=l"(d) : "f"(lo), "f"(hi));
    return d;
}
__device__ __forceinline__ void unpack2(ull v, float& lo, float& hi) {
    asm("mov.b64 {%0, %1}, %2;" : "=f"(lo), "=f"(hi) : "l"(v));
}
__device__ __forceinline__ ull relu2(ull v) {
    float lo, hi;
    unpack2(v, lo, hi);
    return pack2(fmaxf(lo, 0.0f), fmaxf(hi, 0.0f));
}

__global__ void igann_init_kernel(float* __restrict__ out,
                                  const float* __restrict__ bias_b) {
    int i = blockIdx.x * blockDim.x + threadIdx.x;
    if (i < B_TOTAL) out[i] = bias_b[0];
}

__global__ __launch_bounds__(BLOCK, 2)
void igann_kernel(const float* __restrict__ x,
                  const float* __restrict__ linear_a,
                  const float* __restrict__ W1,
                  const float* __restrict__ b1,
                  const float* __restrict__ W2,
                  const float* __restrict__ b2,
                  const float* __restrict__ W3,
                  const float* __restrict__ b3,
                  float* __restrict__ out) {
    extern __shared__ float smem[];
    float* sW2p = smem;                      // [FCHUNK][H][H/2][2]  k-pair interleaved
    float* sW1d = sW2p + W2P_ELE;            // [FCHUNK][H][2] duplicated
    float* sB1d = sW1d + W1D_ELE;            // [FCHUNK][H][2] duplicated
    float* sW3p = sB1d + W1D_ELE;            // [FCHUNK][H/2][2] k-pair
    float* sB2  = sW3p + W3P_ELE;            // [FCHUNK][H] (read as ull pairs)
    float* sB3  = sB2  + FCHUNK * H;         // [FCHUNK]
    float* sA   = sB3  + FCHUNK;             // [FCHUNK]
    float* sx   = sA   + FCHUNK;             // [ROWS][XSTRIDE]

    const int tid  = threadIdx.x;
    const int row0 = blockIdx.x * ROWS;
    const int f0   = blockIdx.y * FCHUNK;

    // ---- stage small weights ----
    {
        const int wbase = f0 * H;
        for (int i = tid; i < FCHUNK * H; i += BLOCK) {
            const float w = W1[wbase + i];
            sW1d[2 * i] = w; sW1d[2 * i + 1] = w;
            const float bb = b1[wbase + i];
            sB1d[2 * i] = bb; sB1d[2 * i + 1] = bb;
            sB2[i] = b2[wbase + i];
            sW3p[i] = W3[wbase + i];   // [f][h] contiguous == [f][kp]{lo,hi}
        }
        if (tid < FCHUNK) {
            sB3[tid] = b3[f0 + tid];
            sA[tid]  = linear_a[f0 + tid];
        }
    }
    // ---- stage W2 k-pair interleaved: sW2p[f][h][kp] = {W2[f][2kp][h], W2[f][2kp+1][h]}
    for (int i = tid; i < FCHUNK * H * (H / 2); i += BLOCK) {
        const int f  = i >> 7;          // / (H * H/2)
        const int h  = (i >> 3) & 15;
        const int kp = i & 7;
        const float* src = W2 + (f0 + f) * (H * H) + h;
        sW2p[2 * i]     = src[(2 * kp) * H];
        sW2p[2 * i + 1] = src[(2 * kp + 1) * H];
    }
    // ---- stage x tile: float4 global loads, scalar smem stores ----
    for (int i = tid; i < ROWS * (FCHUNK / 4); i += BLOCK) {
        const int r = i >> 1;           // FCHUNK/4 == 2 quads per row
        const int q = i & 1;
        const float4 v = *(const float4*)(x + (row0 + r) * F_TOTAL + f0 + 4 * q);
        float* dst = sx + r * XSTRIDE + 4 * q;
        dst[0] = v.x; dst[1] = v.y; dst[2] = v.z; dst[3] = v.w;
    }
    __syncthreads();

    float accL[RPT];
    ull   accP[RPT];
    #pragma unroll
    for (int r = 0; r < RPT; ++r) { accL[r] = 0.0f; accP[r] = pack2(0.0f, 0.0f); }

    #pragma unroll 1
    for (int f = 0; f < FCHUNK; ++f) {
        float xv[RPT];
        #pragma unroll
        for (int r = 0; r < RPT; ++r) xv[r] = sx[(tid + r * BLOCK) * XSTRIDE + f];
        const ull xp01 = pack2(xv[0], xv[1]);
        const ull xp23 = pack2(xv[2], xv[3]);

        const ull* w1d = (const ull*)sW1d + f * H;
        const ull* b1d = (const ull*)sB1d + f * H;
        const ull* b2p = (const ull*)(sB2 + f * H);               // 8 k-pairs
        const ull* w3p = (const ull*)sW3p + f * (H / 2);          // 8 k-pairs
        const ulonglong2* w2q = (const ulonglong2*)sW2p + f * 64; // 16h x 4 quads

        ull t[RPT][8];
        #pragma unroll
        for (int h = 0; h < H; ++h) {
            const ull hp01 = fma2(xp01, w1d[h], b1d[h]);
            const ull hp23 = fma2(xp23, w1d[h], b1d[h]);
            float h0, h1, h2, h3;
            unpack2(hp01, h0, h1);
            unpack2(hp23, h2, h3);
            ull d[RPT];
            d[0] = pack2(fmaxf(h0, 0.0f), fmaxf(h0, 0.0f));
            d[1] = pack2(fmaxf(h1, 0.0f), fmaxf(h1, 0.0f));
            d[2] = pack2(fmaxf(h2, 0.0f), fmaxf(h2, 0.0f));
            d[3] = pack2(fmaxf(h3, 0.0f), fmaxf(h3, 0.0f));
            const ulonglong2* wr = w2q + h * 4;
            #pragma unroll
            for (int j = 0; j < 4; ++j) {
                const ulonglong2 w = wr[j];
                if (h == 0) {
                    const ull c0 = b2p[2 * j];
                    const ull c1 = b2p[2 * j + 1];
                    #pragma unroll
                    for (int r = 0; r < RPT; ++r) {
                        t[r][2 * j]     = fma2(d[r], w.x, c0);
                        t[r][2 * j + 1] = fma2(d[r], w.y, c1);
                    }
                } else {
                    #pragma unroll
                    for (int r = 0; r < RPT; ++r) {
                        t[r][2 * j]     = fma2(d[r], w.x, t[r][2 * j]);
                        t[r][2 * j + 1] = fma2(d[r], w.y, t[r][2 * j + 1]);
                    }
                }
            }
        }
        // epilogue: accP += relu2(t) * w3 pair, per row
        #pragma unroll
        for (int kp = 0; kp < 8; ++kp) {
            const ull w3 = w3p[kp];
            #pragma unroll
            for (int r = 0; r < RPT; ++r)
                accP[r] = fma2(relu2(t[r][kp]), w3, accP[r]);
        }
        const float bf = sB3[f];
        const float af = sA[f];
        #pragma unroll
        for (int r = 0; r < RPT; ++r) accL[r] = fmaf(xv[r], af, accL[r] + bf);
    }

    #pragma unroll
    for (int r = 0; r < RPT; ++r) {
        float lo, hi;
        unpack2(accP[r], lo, hi);
        atomicAdd(&out[row0 + tid + r * BLOCK], accL[r] + lo + hi);
    }
}

extern "C" void kernel_launch(void* const* d_in, const int* in_sizes, int n_in,
                              void* d_out, int out_size) {
    const float* x        = (const float*)d_in[0];
    const float* linear_a = (const float*)d_in[1];
    const float* bias_b   = (const float*)d_in[2];
    const float* W1       = (const float*)d_in[3];
    const float* b1       = (const float*)d_in[4];
    const float* W2       = (const float*)d_in[5];
    const float* b2       = (const float*)d_in[6];
    const float* W3       = (const float*)d_in[7];
    const float* b3       = (const float*)d_in[8];
    float* out = (float*)d_out;

    cudaFuncSetAttribute(igann_kernel,
                         cudaFuncAttributeMaxDynamicSharedMemorySize, SMEM_BYTES);

    igann_init_kernel<<<(B_TOTAL + 255) / 256, 256>>>(out, bias_b);

    dim3 grid(NBTILE, NCHUNK);
    igann_kernel<<<grid, BLOCK, SMEM_BYTES>>>(x, linear_a, W1, b1, W2, b2, W3, b3, out);
}